// round 11
// baseline (speedup 1.0000x reference)
#include <cuda_runtime.h>
#include <math.h>

#define N 32
#define LDT 33                 // padded tile leading dim (conflict-free columns)
#define WARPS_PER_CTA 2
#define NTHREADS (WARPS_PER_CTA * 32)
#define NSWEEP 6
#define MINSWEEP 3
#define JTOL2 1e-6f            // squared scale-free residual tolerance
#define EPS 1e-6f
#define NB_BANDS 9
#define T_DIM 128
#define B_DIM 8

typedef unsigned long long ull;

// ---- packed 2xfp32 helpers (Blackwell FFMA2 path, PTX-only) ----
__device__ __forceinline__ ull pack2(float x, float y)
{ ull r; asm("mov.b64 %0, {%1, %2};" : "=l"(r) : "f"(x), "f"(y)); return r; }
__device__ __forceinline__ void unpack2(ull v, float& x, float& y)
{ asm("mov.b64 {%0, %1}, %2;" : "=f"(x), "=f"(y) : "l"(v)); }
__device__ __forceinline__ ull mul2(ull a, ull b)
{ ull d; asm("mul.rn.f32x2 %0, %1, %2;" : "=l"(d) : "l"(a), "l"(b)); return d; }
__device__ __forceinline__ ull fma2(ull a, ull b, ull c)
{ ull d; asm("fma.rn.f32x2 %0, %1, %2, %3;" : "=l"(d) : "l"(a), "l"(b), "l"(c)); return d; }
__device__ __forceinline__ ull add2(ull a, ull b)
{ ull d; asm("add.rn.f32x2 %0, %1, %2;" : "=l"(d) : "l"(a), "l"(b)); return d; }

// Jacobi rotation for implicit 2x2 [[np, bpq],[bpq, nq]]. MUFU-fast, clamped.
__device__ __forceinline__ void fastrot(float np, float nq, float bpq,
                                        float& c, float& s)
{
    if (fabsf(bpq) > 1e-20f) {
        float tau = __fdividef(nq - np, 2.0f * bpq);
        tau = fminf(fmaxf(tau, -1e15f), 1e15f);
        float t2  = fmaf(tau, tau, 1.0f);
        float den = fabsf(tau) + t2 * rsqrtf(t2);      // |tau| + sqrt(1+tau^2)
        float tt  = __fdividef(1.0f, den);
        tt = (tau >= 0.0f) ? tt : -tt;
        c = rsqrtf(fmaf(tt, tt, 1.0f));
        s = tt * c;
    } else { c = 1.0f; s = 0.0f; }
}

__device__ __forceinline__ const float* site_ptr(const float* x, int site, int t_out)
{
    int band = site % NB_BANDS;
    int tmp  = site / NB_BANDS;
    int tt   = tmp % t_out;
    int b    = tmp / t_out;
    return x + ((size_t)(b * T_DIM + tt) * NB_BANDS + band) * (size_t)(N * N);
}

// ---------------------------------------------------------------------------
// One WARP handles TWO output sites (ILP-2). Per site:
//   L = chol(A); Lb = chol(B); G = L^{-1} Lb  (lane = column, registers)
//   one-sided Jacobi on G's columns (XOR order, packed f32x2, both sites'
//   dependency chains interleaved in every round)
//   mean = Z Z^T with z_c = L g_c * lambda_c^{(w2-1)/2}
// Requires K == 2.
// ---------------------------------------------------------------------------
__global__ void __launch_bounds__(NTHREADS, 6)
wfm_kernel(const float* __restrict__ x, const float* __restrict__ rw,
           float* __restrict__ out, int t_out)
{
    __shared__ float tiles[WARPS_PER_CTA][4][N * LDT];

    const int lane = threadIdx.x & 31;
    const int wrp  = threadIdx.x >> 5;
    float* sL0 = tiles[wrp][0];                // A0 -> L0 (upper zeroed)
    float* sS0 = tiles[wrp][1];                // B0 -> Lb0 -> Z0
    float* sL1 = tiles[wrp][2];                // A1 -> L1 (upper zeroed)
    float* sS1 = tiles[wrp][3];                // B1 -> Lb1 -> Z1

    const int gw    = blockIdx.x * WARPS_PER_CTA + wrp;
    const int site0 = 2 * gw;
    const int site1 = 2 * gw + 1;

    const float* Ma0 = site_ptr(x, site0, t_out);
    const float* Mb0 = Ma0 + (size_t)NB_BANDS * N * N;
    const float* Ma1 = site_ptr(x, site1, t_out);
    const float* Mb1 = Ma1 + (size_t)NB_BANDS * N * N;

    // softmax weight w2 (K == 2)
    float r0 = rw[0], r1 = rw[1];
    float mx = fmaxf(r0, r1);
    float e0 = __expf(r0 - mx), e1 = __expf(r1 - mx);
    const float w2 = e1 / (e0 + e1);

    // load all four matrices (coalesced)
#pragma unroll
    for (int t = 0; t < N; ++t) {
        sL0[t * LDT + lane] = Ma0[t * N + lane];
        sS0[t * LDT + lane] = Mb0[t * N + lane];
        sL1[t * LDT + lane] = Ma1[t * N + lane];
        sS1[t * LDT + lane] = Mb1[t * N + lane];
    }
    __syncwarp();

    // ---- 4-way interleaved Cholesky (rsqrt chains overlap) ----
    for (int k = 0; k < N; ++k) {
        float i0 = rsqrtf(fmaxf(sL0[k * LDT + k], 1e-12f));
        float i1 = rsqrtf(fmaxf(sS0[k * LDT + k], 1e-12f));
        float i2 = rsqrtf(fmaxf(sL1[k * LDT + k], 1e-12f));
        float i3 = rsqrtf(fmaxf(sS1[k * LDT + k], 1e-12f));
        __syncwarp();
        float l0 = 0.f, l1 = 0.f, l2 = 0.f, l3 = 0.f;
        if (lane >= k) {
            l0 = sL0[lane * LDT + k] * i0;  sL0[lane * LDT + k] = l0;
            l1 = sS0[lane * LDT + k] * i1;  sS0[lane * LDT + k] = l1;
            l2 = sL1[lane * LDT + k] * i2;  sL1[lane * LDT + k] = l2;
            l3 = sS1[lane * LDT + k] * i3;  sS1[lane * LDT + k] = l3;
        }
        __syncwarp();
        if (lane > k) {
            for (int j = k + 1; j <= lane; ++j) {
                sL0[lane * LDT + j] -= l0 * sL0[j * LDT + k];
                sS0[lane * LDT + j] -= l1 * sS0[j * LDT + k];
                sL1[lane * LDT + j] -= l2 * sL1[j * LDT + k];
                sS1[lane * LDT + j] -= l3 * sS1[j * LDT + k];
            }
        }
        __syncwarp();
    }

    // zero strict upper of L0, L1 (for unconditional epilogue mm)
#pragma unroll
    for (int j = 0; j < N; ++j)
        if (j > lane) { sL0[lane * LDT + j] = 0.0f; sL1[lane * LDT + j] = 0.0f; }
    __syncwarp();

    // ---- G = L^{-1} Lb for both sites (interleaved forward substitution) ----
    float g0[N], g1[N];
#pragma unroll
    for (int k = 0; k < N; ++k) {
        float a0 = sS0[k * LDT + lane];
        float a1 = sS1[k * LDT + lane];
#pragma unroll
        for (int j = 0; j < k; ++j) {
            a0 -= sL0[k * LDT + j] * g0[j];    // broadcast reads
            a1 -= sL1[k * LDT + j] * g1[j];
        }
        float v0 = a0 * __fdividef(1.0f, sL0[k * LDT + k]);
        float v1 = a1 * __fdividef(1.0f, sL1[k * LDT + k]);
        g0[k] = (k >= lane) ? v0 : 0.0f;
        g1[k] = (k >= lane) ? v1 : 0.0f;
    }

    // pack both columns
    ull u20[N / 2], u21[N / 2];
#pragma unroll
    for (int i = 0; i < N / 2; ++i) {
        u20[i] = pack2(g0[2 * i], g0[2 * i + 1]);
        u21[i] = pack2(g1[2 * i], g1[2 * i + 1]);
    }

    float nu0, nu1;
    {
        ull a0 = 0ull, a1 = 0ull;
#pragma unroll
        for (int i = 0; i < N / 2; ++i) {
            a0 = fma2(u20[i], u20[i], a0);
            a1 = fma2(u21[i], u21[i], a1);
        }
        float ax, ay;
        unpack2(a0, ax, ay); nu0 = ax + ay;
        unpack2(a1, ax, ay); nu1 = ax + ay;
    }

    // ---------------- one-sided Jacobi, XOR order, two interleaved streams --
#pragma unroll 1
    for (int sweep = 0; sweep < NSWEEP; ++sweep) {
        bool bad = false;
#pragma unroll 1
        for (int m = 1; m < 32; ++m) {
            const int partner = lane ^ m;
            const bool isp = lane < partner;

            ull pu0[N / 2], pu1[N / 2];
#pragma unroll
            for (int i = 0; i < N / 2; ++i)
                pu0[i] = __shfl_xor_sync(0xffffffffu, u20[i], m);
#pragma unroll
            for (int i = 0; i < N / 2; ++i)
                pu1[i] = __shfl_xor_sync(0xffffffffu, u21[i], m);
            float pn0 = __shfl_xor_sync(0xffffffffu, nu0, m);
            float pn1 = __shfl_xor_sync(0xffffffffu, nu1, m);

            // pair dots, 4 parallel chains each (same grouping in pair lanes)
            ull a00 = 0ull, a01 = 0ull, a02 = 0ull, a03 = 0ull;
            ull a10 = 0ull, a11 = 0ull, a12 = 0ull, a13 = 0ull;
#pragma unroll
            for (int i = 0; i < N / 2; i += 4) {
                a00 = fma2(u20[i + 0], pu0[i + 0], a00);
                a01 = fma2(u20[i + 1], pu0[i + 1], a01);
                a02 = fma2(u20[i + 2], pu0[i + 2], a02);
                a03 = fma2(u20[i + 3], pu0[i + 3], a03);
                a10 = fma2(u21[i + 0], pu1[i + 0], a10);
                a11 = fma2(u21[i + 1], pu1[i + 1], a11);
                a12 = fma2(u21[i + 2], pu1[i + 2], a12);
                a13 = fma2(u21[i + 3], pu1[i + 3], a13);
            }
            float bu0, bu1;
            {
                ull d0 = add2(add2(a00, a01), add2(a02, a03));
                ull d1 = add2(add2(a10, a11), add2(a12, a13));
                float dx, dy;
                unpack2(d0, dx, dy); bu0 = dx + dy;
                unpack2(d1, dx, dy); bu1 = dx + dy;
            }

            bad |= (bu0 * bu0 > nu0 * pn0 * JTOL2);
            bad |= (bu1 * bu1 > nu1 * pn1 * JTOL2);

            float np0 = isp ? nu0 : pn0, nq0 = isp ? pn0 : nu0;
            float np1 = isp ? nu1 : pn1, nq1 = isp ? pn1 : nu1;

            float c0, s0, c1, s1;
            fastrot(np0, nq0, bu0, c0, s0);
            fastrot(np1, nq1, bu1, c1, s1);
            float ss0 = isp ? -s0 : s0;
            float ss1 = isp ? -s1 : s1;

            ull c20  = pack2(c0, c0),  ss20 = pack2(ss0, ss0);
            ull c21  = pack2(c1, c1),  ss21 = pack2(ss1, ss1);
#pragma unroll
            for (int i = 0; i < N / 2; ++i) {
                u20[i] = fma2(ss20, pu0[i], mul2(c20, u20[i]));
                u21[i] = fma2(ss21, pu1[i], mul2(c21, u21[i]));
            }

            // exact norm rotation identities
            nu0 = c0 * c0 * nu0 + s0 * s0 * pn0 + 2.0f * ss0 * c0 * bu0;
            nu1 = c1 * c1 * nu1 + s1 * s1 * pn1 + 2.0f * ss1 * c1 * bu1;
        }
        if (sweep >= MINSWEEP - 1 && !__any_sync(0xffffffffu, bad)) break;
    }

    // ---- scale columns: z = L u * lam^{(w2-1)/2} (both sites) ----
    float lam0, lam1;
    {
        ull a0 = 0ull, a1 = 0ull;
#pragma unroll
        for (int i = 0; i < N / 2; ++i) {
            a0 = fma2(u20[i], u20[i], a0);
            a1 = fma2(u21[i], u21[i], a1);
        }
        float ax, ay;
        unpack2(a0, ax, ay); lam0 = fmaxf(ax + ay, EPS);
        unpack2(a1, ax, ay); lam1 = fmaxf(ax + ay, EPS);
    }
    float sc0 = __expf(0.5f * (w2 - 1.0f) * __logf(lam0));
    float sc1 = __expf(0.5f * (w2 - 1.0f) * __logf(lam1));

#pragma unroll
    for (int i = 0; i < N / 2; ++i) {
        unpack2(u20[i], g0[2 * i], g0[2 * i + 1]);
        unpack2(u21[i], g1[2 * i], g1[2 * i + 1]);
    }
#pragma unroll
    for (int i = 0; i < N; ++i) { g0[i] *= sc0; g1[i] *= sc1; }

    __syncwarp();
    // Z = L * u for both sites (interleaved), stored into the S tiles
    for (int i = 0; i < N; ++i) {
        float acc0 = 0.0f, acc1 = 0.0f;
#pragma unroll
        for (int j = 0; j < N; ++j) {
            acc0 = fmaf(sL0[i * LDT + j], g0[j], acc0);  // upper zeroed
            acc1 = fmaf(sL1[i * LDT + j], g1[j], acc1);
        }
        sS0[i * LDT + lane] = acc0;
        sS1[i * LDT + lane] = acc1;
    }
    __syncwarp();

    // mean = Z Z^T, one site at a time (limits register pressure)
    {
        float rr[N];
#pragma unroll
        for (int c = 0; c < N; ++c) rr[c] = sS0[lane * LDT + c];
        float* o = out + (size_t)site0 * (N * N);
        for (int i = 0; i < N; ++i) {
            float acc = 0.0f;
#pragma unroll
            for (int c = 0; c < N; ++c)
                acc = fmaf(sS0[i * LDT + c], rr[c], acc);
            o[i * N + lane] = acc;
        }
    }
    {
        float rr[N];
#pragma unroll
        for (int c = 0; c < N; ++c) rr[c] = sS1[lane * LDT + c];
        float* o = out + (size_t)site1 * (N * N);
        for (int i = 0; i < N; ++i) {
            float acc = 0.0f;
#pragma unroll
            for (int c = 0; c < N; ++c)
                acc = fmaf(sS1[i * LDT + c], rr[c], acc);
            o[i * N + lane] = acc;
        }
    }
}

extern "C" void kernel_launch(void* const* d_in, const int* in_sizes, int n_in,
                              void* d_out, int out_size)
{
    const float* x  = (const float*)d_in[0];
    const float* rw = (const float*)d_in[1];
    float* out = (float*)d_out;

    const int K     = in_sizes[1];               // KERNEL_SIZE (= 2 for this problem)
    const int t_out = T_DIM - K + 1;             // 127
    const int sites = B_DIM * t_out * NB_BANDS;  // 9144 (even)
    const int warps = sites / 2;                 // 2 sites per warp
    const int nblocks = warps / WARPS_PER_CTA;   // 2286

    wfm_kernel<<<nblocks, NTHREADS>>>(x, rw, out, t_out);
}